// round 13
// baseline (speedup 1.0000x reference)
#include <cuda_runtime.h>
#include <cstdint>

// Problem constants (fixed by the dataset)
#define B_   16
#define S_   2048
#define D_   1024
#define P_   8192
#define R_   16

#define LCH  16               // rows per chunk (MAX_SPAN=32 => spans cross <=2 boundaries)
#define NCH  (S_ / LCH)       // 128 chunks
#define OUTW (2 * D_ + R_)    // 2064 floats per output row

#define NPH  2                // batch phases
#define GB   (B_ / NPH)       // 8 batches per phase

// arr[b][s][d]: within-chunk inclusive prefix (flagged rows only)
__device__ float g_arr[(size_t)B_ * S_ * D_];            // address space ~134 MB
__device__ float g_part[(size_t)B_ * NCH * D_];          // chunk totals (8 MB, L2-resident)
__device__ int   g_flag[(B_ * S_) / 4];                  // packed byte flags; zero at module load

// ---------------------------------------------------------------------------
// Mark rows of arr that pairs will read: for endpoint e>0, row (e-1) of batch b.
// IDEMPOTENT: only sets bytes to 1 from identical inputs on every call ->
// no zeroing pass needed (__device__ globals are zero-initialized at load).
__global__ void k_mark(const int* __restrict__ batch_idx,
                       const int* __restrict__ e1s, const int* __restrict__ e1e,
                       const int* __restrict__ e2s, const int* __restrict__ e2e) {
    int i = blockIdx.x * blockDim.x + threadIdx.x;      // [0, 4P)
    if (i >= 4 * P_) return;
    int p = i & (P_ - 1);
    int which = i >> 13;                                 // P = 8192 = 2^13
    int e;
    switch (which) {
        case 0: e = e1s[p]; break;
        case 1: e = e1e[p]; break;
        case 2: e = e2s[p]; break;
        default: e = e2e[p]; break;
    }
    if (e > 0) ((unsigned char*)g_flag)[batch_idx[p] * S_ + (e - 1)] = 1;
}

// ---------------------------------------------------------------------------
// Prefix pass over ONE batch phase (GB batches). Grid = GB*NCH = 1024 blocks
// x 256 threads = 262K threads (the proven full-bandwidth shape): full-width
// contiguous rows, high occupancy. tok read once -> .cs streaming; arr/part
// writes stay L2-resident (~42 MB + 4 MB) for the following pairs phase.
__global__ void __launch_bounds__(256)
k_prefix_phase(const float* __restrict__ tok, int ph) {
    __shared__ unsigned char sflag[LCH];
    int b  = ph * GB + (blockIdx.x >> 7);                // NCH = 128
    int ch = blockIdx.x & (NCH - 1);
    int d4 = threadIdx.x;                                // 256 float4 lanes

    if (threadIdx.x < LCH)
        sflag[threadIdx.x] = ((const unsigned char*)g_flag)[b * S_ + ch * LCH + threadIdx.x];
    __syncthreads();

    const float4* t  = (const float4*)(tok   + ((size_t)b * S_ + (size_t)ch * LCH) * D_) + d4;
    float4*       ar = (float4*)      (g_arr + ((size_t)b * S_ + (size_t)ch * LCH) * D_) + d4;

    float4 run = make_float4(0.f, 0.f, 0.f, 0.f);
#pragma unroll
    for (int i = 0; i < LCH; ++i) {
        float4 v = __ldcs(t + (size_t)i * (D_ / 4));     // streaming read
        run.x += v.x; run.y += v.y; run.z += v.z; run.w += v.w;
        if (sflag[i]) ar[(size_t)i * (D_ / 4)] = run;    // keep in L2
    }
    ((float4*)(g_part + ((size_t)b * NCH + ch) * D_))[d4] = run;
}

// ---------------------------------------------------------------------------
// Span numerator with 16-row chunks (verified round 11). For span (s, f]:
//   num = arr[f-1] - (s>0 ? arr[s-1] : 0) + sum_{c in [cbs', cbf)} part[c]
// where cbs' = (s>0) ? (s-1)/16 : 0, cbf = (f-1)/16; 0..2 part adds (L2-hot).
__device__ __forceinline__ float4 span_num(const float4* arr_b, const float4* part_b,
                                           int s, int f, int t) {
    float4 r = arr_b[(size_t)(f - 1) * (D_ / 4) + t];
    int cbf = (f - 1) >> 4;
    int cbs = 0;
    if (s > 0) {
        float4 lo = arr_b[(size_t)(s - 1) * (D_ / 4) + t];
        r.x -= lo.x; r.y -= lo.y; r.z -= lo.z; r.w -= lo.w;
        cbs = (s - 1) >> 4;
    }
    for (int c = cbs; c < cbf; ++c) {
        float4 br = part_b[(size_t)c * (D_ / 4) + t];
        r.x += br.x; r.y += br.y; r.z += br.z; r.w += br.w;
    }
    return r;
}

// Pairs pass for ONE batch phase. 512 threads = 2 pairs per block; pairs whose
// batch is outside this phase exit after one L2-hit index load. arr reads for
// this phase's batches are L2-resident from the preceding prefix phase.
__global__ void __launch_bounds__(512)
k_pairs_phase(const int* __restrict__ batch_idx,
              const int* __restrict__ e1s, const int* __restrict__ e1e,
              const int* __restrict__ e2s, const int* __restrict__ e2e,
              const int* __restrict__ rel_idx,
              const float* __restrict__ rel_table,
              float* __restrict__ out, int ph) {
    int p = blockIdx.x * 2 + (threadIdx.x >> 8);
    int t = threadIdx.x & 255;          // float4 lane

    int b = __ldg(batch_idx + p);
    if ((b >> 3) != ph) return;         // handled by the other phase (GB = 8)

    int s1 = __ldg(e1s + p), f1 = __ldg(e1e + p);
    int s2 = __ldg(e2s + p), f2 = __ldg(e2e + p);

    const float4* arr_b  = (const float4*)(g_arr  + (size_t)b * S_ * D_);
    const float4* part_b = (const float4*)(g_part + (size_t)b * NCH * D_);
    float4* orow = (float4*)(out + (size_t)p * OUTW);

    float inv1 = 1.0f / (float)(f1 - s1);
    float inv2 = 1.0f / (float)(f2 - s2);

    float4 n1 = span_num(arr_b, part_b, s1, f1, t);
    __stcs(orow + t, make_float4(n1.x * inv1, n1.y * inv1, n1.z * inv1, n1.w * inv1));

    float4 n2 = span_num(arr_b, part_b, s2, f2, t);
    __stcs(orow + D_ / 4 + t,
           make_float4(n2.x * inv2, n2.y * inv2, n2.z * inv2, n2.w * inv2));

    if (t < R_) {
        int ri = __ldg(rel_idx + p);
        __stcs(out + (size_t)p * OUTW + 2 * D_ + t,
               __ldg(rel_table + (size_t)ri * R_ + t));
    }
}

// ---------------------------------------------------------------------------
extern "C" void kernel_launch(void* const* d_in, const int* in_sizes, int n_in,
                              void* d_out, int out_size) {
    const float* tok       = (const float*)d_in[0];
    const int*   batch_idx = (const int*)d_in[1];
    const int*   e1s       = (const int*)d_in[2];
    const int*   e1e       = (const int*)d_in[3];
    const int*   e2s       = (const int*)d_in[4];
    const int*   e2e       = (const int*)d_in[5];
    const int*   rel_idx   = (const int*)d_in[6];
    const float* rel_table = (const float*)d_in[7];
    float* out = (float*)d_out;

    (void)in_sizes; (void)n_in; (void)out_size;

    k_mark<<<(4 * P_) / 256, 256>>>(batch_idx, e1s, e1e, e2s, e2e);

    for (int ph = 0; ph < NPH; ++ph) {
        k_prefix_phase<<<GB * NCH, 256>>>(tok, ph);
        k_pairs_phase<<<P_ / 2, 512>>>(batch_idx, e1s, e1e, e2s, e2e,
                                       rel_idx, rel_table, out, ph);
    }
}

// round 14
// speedup vs baseline: 1.2698x; 1.2698x over previous
#include <cuda_runtime.h>
#include <cstdint>

// Problem constants (fixed by the dataset)
#define B_   16
#define S_   2048
#define D_   1024
#define P_   8192
#define R_   16

#define LCH  32               // rows per chunk == MAX_SPAN (load-bearing!)
#define NCH  (S_ / LCH)       // 64 chunks
#define OUTW (2 * D_ + R_)    // 2064 floats per output row

#define PAIRS_PER_BLK 2

// arr[b][s][d]: inclusive prefix of tok within the chunk containing s (flagged rows only)
__device__ float g_arr[(size_t)B_ * S_ * D_];            // ~134 MB address space, ~83 MB touched
__device__ float g_part[(size_t)B_ * NCH * D_];          // chunk totals (4 MB, L2-resident)
__device__ int   g_flag[(B_ * S_) / 4];                  // packed byte flags; zero at module load

// ---------------------------------------------------------------------------
// Fused mark + rel-emit. Thread i (of 4P):
//   * marks endpoint (i>>13) of pair (i & 8191): for e>0, flag row (e-1) of batch b
//   * writes rel float4 quarter (i>>13) of pair (i & 8191) into out
// Marking is IDEMPOTENT (only sets bytes to 1 from identical inputs each call;
// __device__ globals are zero-initialized at module load -> no zeroing pass).
// The rel columns are independent of the prefix, so they hide under this
// latency-bound kernel's idle bandwidth instead of k_pairs' tail.
__global__ void k_mark_rel(const int* __restrict__ batch_idx,
                           const int* __restrict__ e1s, const int* __restrict__ e1e,
                           const int* __restrict__ e2s, const int* __restrict__ e2e,
                           const int* __restrict__ rel_idx,
                           const float* __restrict__ rel_table,
                           float* __restrict__ out) {
    int i = blockIdx.x * blockDim.x + threadIdx.x;      // [0, 4P)
    if (i >= 4 * P_) return;
    int p = i & (P_ - 1);
    int which = i >> 13;                                 // P = 8192 = 2^13

    // rel quarter: out[p][2D + 4*which .. +3] = rel_table[rel_idx[p]][4*which ..]
    int ri = __ldg(rel_idx + p);
    float4 rv = *(const float4*)(rel_table + (size_t)ri * R_ + which * 4);
    __stcs((float4*)(out + (size_t)p * OUTW + 2 * D_) + which, rv);

    int e;
    switch (which) {
        case 0: e = __ldg(e1s + p); break;
        case 1: e = __ldg(e1e + p); break;
        case 2: e = __ldg(e2s + p); break;
        default: e = __ldg(e2e + p); break;
    }
    if (e > 0) ((unsigned char*)g_flag)[__ldg(batch_idx + p) * S_ + (e - 1)] = 1;
}

// ---------------------------------------------------------------------------
// Single full-width tok pass (the measured 6.2 TB/s shape): per (b, chunk, d4)
// running prefix; write only flagged rows; emit chunk total unconditionally.
// tok read ONCE -> streaming (.cs) loads so arr/part stay L2-preferred.
__global__ void k_local_prefix(const float* __restrict__ tok) {
    __shared__ unsigned char sflag[LCH];
    int idx = blockIdx.x * blockDim.x + threadIdx.x;
    int d4   = idx & (D_ / 4 - 1);
    int rest = idx >> 8;                                  // D/4 = 256
    int ch   = rest & (NCH - 1);
    int b    = rest >> 6;                                 // NCH = 64

    if (threadIdx.x < LCH)
        sflag[threadIdx.x] = ((const unsigned char*)g_flag)[b * S_ + ch * LCH + threadIdx.x];
    __syncthreads();

    const float4* t  = (const float4*)(tok   + ((size_t)b * S_ + (size_t)ch * LCH) * D_) + d4;
    float4*       ar = (float4*)      (g_arr + ((size_t)b * S_ + (size_t)ch * LCH) * D_) + d4;

    float4 run = make_float4(0.f, 0.f, 0.f, 0.f);
#pragma unroll
    for (int i = 0; i < LCH; ++i) {
        float4 v = __ldcs(t + (size_t)i * (D_ / 4));     // streaming read
        run.x += v.x; run.y += v.y; run.z += v.z; run.w += v.w;
        if (sflag[i]) ar[(size_t)i * (D_ / 4)] = run;    // keep in L2
    }
    ((float4*)(g_part + ((size_t)b * NCH + ch) * D_))[d4] = run;
}

// ---------------------------------------------------------------------------
// Span numerator: span <= LCH => endpoints in same or adjacent chunks:
//   s == 0           : cs[e] = arr[e-1]
//   same chunk       : cs[e]-cs[s] = arr[e-1] - arr[s-1]
//   adjacent chunks  : cs[e]-cs[s] = arr[e-1] - arr[s-1] + part[chunk(s-1)]
__device__ __forceinline__ float4 span_num(const float4* arr_b, const float4* part_b,
                                           int s, int f, int t) {
    float4 r = arr_b[(size_t)(f - 1) * (D_ / 4) + t];
    if (s > 0) {
        float4 lo = arr_b[(size_t)(s - 1) * (D_ / 4) + t];
        r.x -= lo.x; r.y -= lo.y; r.z -= lo.z; r.w -= lo.w;
        int cbs = (s - 1) >> 5;                 // LCH = 32
        int cbf = (f - 1) >> 5;
        if (cbf != cbs) {
            float4 br = part_b[(size_t)cbs * (D_ / 4) + t];
            r.x += br.x; r.y += br.y; r.z += br.z; r.w += br.w;
        }
    }
    return r;
}

// Best-measured pairs shape: 512 threads = 2 pairs per block, 256 lanes each;
// out written with streaming stores so arr keeps L2 priority. Rel columns are
// already written by k_mark_rel.
__global__ void k_pairs(const int* __restrict__ batch_idx,
                        const int* __restrict__ e1s, const int* __restrict__ e1e,
                        const int* __restrict__ e2s, const int* __restrict__ e2e,
                        float* __restrict__ out) {
    int p = blockIdx.x * PAIRS_PER_BLK + (threadIdx.x >> 8);
    int t = threadIdx.x & 255;          // float4 lane

    int b  = __ldg(batch_idx + p);
    int s1 = __ldg(e1s + p), f1 = __ldg(e1e + p);
    int s2 = __ldg(e2s + p), f2 = __ldg(e2e + p);

    const float4* arr_b  = (const float4*)(g_arr  + (size_t)b * S_ * D_);
    const float4* part_b = (const float4*)(g_part + (size_t)b * NCH * D_);
    float4* orow = (float4*)(out + (size_t)p * OUTW);

    float inv1 = 1.0f / (float)(f1 - s1);
    float inv2 = 1.0f / (float)(f2 - s2);

    float4 n1 = span_num(arr_b, part_b, s1, f1, t);
    __stcs(orow + t, make_float4(n1.x * inv1, n1.y * inv1, n1.z * inv1, n1.w * inv1));

    float4 n2 = span_num(arr_b, part_b, s2, f2, t);
    __stcs(orow + D_ / 4 + t,
           make_float4(n2.x * inv2, n2.y * inv2, n2.z * inv2, n2.w * inv2));
}

// ---------------------------------------------------------------------------
extern "C" void kernel_launch(void* const* d_in, const int* in_sizes, int n_in,
                              void* d_out, int out_size) {
    const float* tok       = (const float*)d_in[0];
    const int*   batch_idx = (const int*)d_in[1];
    const int*   e1s       = (const int*)d_in[2];
    const int*   e1e       = (const int*)d_in[3];
    const int*   e2s       = (const int*)d_in[4];
    const int*   e2e       = (const int*)d_in[5];
    const int*   rel_idx   = (const int*)d_in[6];
    const float* rel_table = (const float*)d_in[7];
    float* out = (float*)d_out;

    (void)in_sizes; (void)n_in; (void)out_size;

    k_mark_rel<<<(4 * P_) / 256, 256>>>(batch_idx, e1s, e1e, e2s, e2e,
                                        rel_idx, rel_table, out);
    k_local_prefix<<<B_ * NCH * (D_ / 4) / 256, 256>>>(tok);
    k_pairs<<<P_ / PAIRS_PER_BLK, 256 * PAIRS_PER_BLK>>>(batch_idx, e1s, e1e, e2s, e2e, out);
}